// round 5
// baseline (speedup 1.0000x reference)
#include <cuda_runtime.h>

// y[b,t,c*S+s] = x[b,t,c] * w[c*S+s]
// B=512, T=128, C=128, S=32, OUT_DIM=4096. Output = 1 GiB fp32, write-bound.
//
// R5 = R2 geometry (2 rows/block, 256 thr, 32768 blocks) but with 256-bit
// stores (st.global.cs.v8.f32, sm_100+): 4 STG.256/thread instead of
// 8 STG.128. At float8 granularity each thread needs only TWO distinct w
// vectors ((k*256+tid)&511 alternates tid / 256+tid), kept in registers.

#define THREADS      256
#define ROWS         2
#define F8_PER_BLOCK 1024            // 2 rows * 4096 floats / 8
#define ITERS        4               // 1024 / 256

__global__ __launch_bounds__(THREADS, 8)
void csi_embedding_kernel(const float* __restrict__ x,
                          const float* __restrict__ w,
                          float*       __restrict__ out)
{
    __shared__ float s_x[ROWS * 128];    // 1 KiB

    const int tid = threadIdx.x;

    // Two w float8s per thread, 256-bit loads (L1/L2-hit after first blocks)
    float w0[8], w1[8];
    {
        const float* p0 = w + (unsigned)tid * 8u;          // float8 idx tid
        const float* p1 = w + (unsigned)(256 + tid) * 8u;  // float8 idx 256+tid
        asm volatile("ld.global.nc.v8.f32 {%0,%1,%2,%3,%4,%5,%6,%7}, [%8];"
                     : "=f"(w0[0]), "=f"(w0[1]), "=f"(w0[2]), "=f"(w0[3]),
                       "=f"(w0[4]), "=f"(w0[5]), "=f"(w0[6]), "=f"(w0[7])
                     : "l"(p0));
        asm volatile("ld.global.nc.v8.f32 {%0,%1,%2,%3,%4,%5,%6,%7}, [%8];"
                     : "=f"(w1[0]), "=f"(w1[1]), "=f"(w1[2]), "=f"(w1[3]),
                       "=f"(w1[4]), "=f"(w1[5]), "=f"(w1[6]), "=f"(w1[7])
                     : "l"(p1));
    }

    // Stage x: 256 consecutive floats = rows [2*bid, 2*bid+1], coalesced
    s_x[tid] = __ldg(&x[blockIdx.x * (ROWS * 128) + tid]);

    __syncthreads();

    const long long base = (long long)blockIdx.x * (F8_PER_BLOCK * 8); // floats

    #pragma unroll
    for (int k = 0; k < ITERS; k++) {
        int pos8 = k * THREADS + tid;                 // 0..1023, float8 index
        // row_local = pos8>>9 ; channel = (pos8 & 511) >> 2  (4 float8 per channel)
        float xs = s_x[((pos8 >> 9) << 7) + ((pos8 & 511) >> 2)];

        const float* wv = (k & 1) ? w1 : w0;          // compile-time per k

        float r0 = xs * wv[0], r1 = xs * wv[1], r2 = xs * wv[2], r3 = xs * wv[3];
        float r4 = xs * wv[4], r5 = xs * wv[5], r6 = xs * wv[6], r7 = xs * wv[7];

        float* p = out + base + (long long)pos8 * 8;
        asm volatile("st.global.cs.v8.f32 [%0], {%1,%2,%3,%4,%5,%6,%7,%8};"
                     :: "l"(p),
                        "f"(r0), "f"(r1), "f"(r2), "f"(r3),
                        "f"(r4), "f"(r5), "f"(r6), "f"(r7)
                     : "memory");
    }
}

extern "C" void kernel_launch(void* const* d_in, const int* in_sizes, int n_in,
                              void* d_out, int out_size)
{
    const float* x = (const float*)d_in[0];
    const float* w = (const float*)d_in[1];
    float* out = (float*)d_out;

    // out_size floats / 8192 per block = 32768 blocks
    int blocks = out_size / (F8_PER_BLOCK * 8);
    csi_embedding_kernel<<<blocks, THREADS>>>(x, w, out);
}